// round 10
// baseline (speedup 1.0000x reference)
#include <cuda_runtime.h>
#include <cuda_fp16.h>
#include <cstdint>

#define NN 100000
#define EE 3200000
#define DD 128
#define BN_EPS 1e-5f
#define NBLK 98   // ceil(NN/1024)

// ---- scratch (device globals) ----
__device__ int    g_count[NN];
__device__ int    g_offset[NN];
__device__ int    g_blksum[NBLK];
__device__ int    g_blkoff[NBLK];
__device__ int    g_rank[EE];
__device__ int    g_edge_src[EE];
__device__ __half g_h16[(size_t)NN * DD];
__device__ __half g_neigh16[(size_t)NN * DD];
__device__ __half g_rst16[(size_t)NN * DD];
__device__ __half g_Wt16[128 * 256];   // [n][k] fp16 W^T over [W_self; W_neigh]
__device__ float  g_colsum[DD];
__device__ float  g_colsumsq[DD];
__device__ float  g_scale[DD];
__device__ float  g_shift[DD];

// ================= helpers =================
__device__ __forceinline__ uint32_t smem_u32(const void* p) {
    uint32_t a;
    asm("{ .reg .u64 t; cvta.to.shared.u64 t, %1; cvt.u32.u64 %0, t; }" : "=r"(a) : "l"(p));
    return a;
}
__device__ __forceinline__ void cp16(uint32_t saddr, const void* gaddr, bool valid) {
    asm volatile("cp.async.cg.shared.global [%0], [%1], 16, %2;"
                 :: "r"(saddr), "l"(gaddr), "r"(valid ? 16u : 0u) : "memory");
}
#define CP_COMMIT() asm volatile("cp.async.commit_group;" ::: "memory")
#define CP_WAIT0()  asm volatile("cp.async.wait_group 0;" ::: "memory")

__device__ __forceinline__ void mma16(float* d, uint32_t a0, uint32_t a1, uint32_t a2,
                                      uint32_t a3, uint32_t b0, uint32_t b1) {
    asm volatile(
        "mma.sync.aligned.m16n8k16.row.col.f32.f16.f16.f32 "
        "{%0,%1,%2,%3}, {%4,%5,%6,%7}, {%8,%9}, {%0,%1,%2,%3};"
        : "+f"(d[0]), "+f"(d[1]), "+f"(d[2]), "+f"(d[3])
        : "r"(a0), "r"(a1), "r"(a2), "r"(a3), "r"(b0), "r"(b1));
}

// ---------------------------------------------------------------- zero
__global__ void k_zero() {
    int i = blockIdx.x * blockDim.x + threadIdx.x;
    if (i < NN) g_count[i] = 0;
    if (i < DD) { g_colsum[i] = 0.f; g_colsumsq[i] = 0.f; }
}

// ---------------------------------------------------------------- h -> fp16 copy
__global__ void k_h16(const float* __restrict__ h) {
    int i = blockIdx.x * blockDim.x + threadIdx.x;   // one per 8 floats
    const int TOT = NN * DD / 8;
    if (i >= TOT) return;
    float4 a = ((const float4*)h)[2 * i];
    float4 b = ((const float4*)h)[2 * i + 1];
    __half2 r[4];
    r[0] = __float22half2_rn(make_float2(a.x, a.y));
    r[1] = __float22half2_rn(make_float2(a.z, a.w));
    r[2] = __float22half2_rn(make_float2(b.x, b.y));
    r[3] = __float22half2_rn(make_float2(b.z, b.w));
    ((uint4*)g_h16)[i] = *(uint4*)r;
}

// ---------------------------------------------------------------- W transpose + fp16 round
__global__ void k_wt(const float* __restrict__ Ws, const float* __restrict__ Wn) {
    int i = blockIdx.x * blockDim.x + threadIdx.x;
    if (i >= 128 * 256) return;
    int n = i >> 8, k = i & 255;
    float v = (k < 128) ? Ws[(size_t)k * DD + n] : Wn[(size_t)(k - 128) * DD + n];
    g_Wt16[i] = __float2half_rn(v);
}

// ---------------------------------------------------------------- degree histogram + edge rank (4-wide)
__global__ void k_hist(const int* __restrict__ dst) {
    int e4 = blockIdx.x * blockDim.x + threadIdx.x;
    if (e4 >= EE / 4) return;
    int4 d = ((const int4*)dst)[e4];
    int4 r;
    r.x = atomicAdd(&g_count[d.x], 1);
    r.y = atomicAdd(&g_count[d.y], 1);
    r.z = atomicAdd(&g_count[d.z], 1);
    r.w = atomicAdd(&g_count[d.w], 1);
    ((int4*)g_rank)[e4] = r;
}

// ---------------------------------------------------------------- scan phase 1: per-block
__global__ void k_scan_blk() {
    __shared__ int wsum[32];
    int t = threadIdx.x;
    int i = blockIdx.x * 1024 + t;
    int lane = t & 31, wid = t >> 5;
    int v = (i < NN) ? g_count[i] : 0;
    int x = v;
#pragma unroll
    for (int o = 1; o < 32; o <<= 1) {
        int y = __shfl_up_sync(0xffffffffu, x, o);
        if (lane >= o) x += y;
    }
    if (lane == 31) wsum[wid] = x;
    __syncthreads();
    if (wid == 0) {
        int s = wsum[lane];
#pragma unroll
        for (int o = 1; o < 32; o <<= 1) {
            int y = __shfl_up_sync(0xffffffffu, s, o);
            if (lane >= o) s += y;
        }
        wsum[lane] = s;
    }
    __syncthreads();
    int warpoff = (wid == 0) ? 0 : wsum[wid - 1];
    if (i < NN) g_offset[i] = warpoff + x - v;
    if (t == 1023) g_blksum[blockIdx.x] = warpoff + x;
}

// ---------------------------------------------------------------- scan phase 2: block totals
__global__ void k_scan_top() {
    __shared__ int wsum[4];
    int t = threadIdx.x;            // 128 threads
    int lane = t & 31, wid = t >> 5;
    int v = (t < NBLK) ? g_blksum[t] : 0;
    int x = v;
#pragma unroll
    for (int o = 1; o < 32; o <<= 1) {
        int y = __shfl_up_sync(0xffffffffu, x, o);
        if (lane >= o) x += y;
    }
    if (lane == 31) wsum[wid] = x;
    __syncthreads();
    int woff = 0;
    for (int w = 0; w < wid; w++) woff += wsum[w];
    if (t < NBLK) g_blkoff[t] = woff + x - v;
}

// ---------------------------------------------------------------- scan phase 3: add offsets
__global__ void k_scan_add() {
    int i = blockIdx.x * 1024 + threadIdx.x;
    if (i < NN) g_offset[i] += g_blkoff[blockIdx.x];
}

// ---------------------------------------------------------------- scatter into CSR (no atomics, 4-wide)
__global__ void k_scatter(const int* __restrict__ src,
                          const int* __restrict__ dst) {
    int e4 = blockIdx.x * blockDim.x + threadIdx.x;
    if (e4 >= EE / 4) return;
    int4 d = ((const int4*)dst)[e4];
    int4 s = ((const int4*)src)[e4];
    int4 r = ((const int4*)g_rank)[e4];
    g_edge_src[g_offset[d.x] + r.x] = s.x;
    g_edge_src[g_offset[d.y] + r.y] = s.y;
    g_edge_src[g_offset[d.z] + r.z] = s.z;
    g_edge_src[g_offset[d.w] + r.w] = s.w;
}

// ---------------------------------------------------------------- segment mean (1 warp / node)
// 16 lanes x 16B per edge row; warp processes 2 edges per step (lane-half = edge).
__global__ void k_aggregate() {
    int gwarp = (blockIdx.x * blockDim.x + threadIdx.x) >> 5;
    if (gwarp >= NN) return;
    int lane = threadIdx.x & 31;
    int half = lane >> 4;           // which edge of the pair
    int hl = lane & 15;             // owns cols hl*8 .. hl*8+7
    int start = g_offset[gwarp];
    int deg = g_count[gwarp];

    const uint4* hbase = (const uint4*)g_h16;   // 16 uint4 per row

    float acc[8] = {0, 0, 0, 0, 0, 0, 0, 0};

    int i = 0;
    for (; i + 32 <= deg; i += 32) {
        int s = g_edge_src[start + i + lane];
#pragma unroll
        for (int j = 0; j < 32; j += 2) {
            int sj = __shfl_sync(0xffffffffu, s, j + half);
            uint4 u = hbase[(size_t)sj * 16 + hl];
            float2 f0 = __half22float2(*(__half2*)&u.x);
            float2 f1 = __half22float2(*(__half2*)&u.y);
            float2 f2 = __half22float2(*(__half2*)&u.z);
            float2 f3 = __half22float2(*(__half2*)&u.w);
            acc[0] += f0.x; acc[1] += f0.y; acc[2] += f1.x; acc[3] += f1.y;
            acc[4] += f2.x; acc[5] += f2.y; acc[6] += f3.x; acc[7] += f3.y;
        }
    }
    int rem = deg - i;
    if (rem) {
        int s = (lane < rem) ? g_edge_src[start + i + lane] : 0;
        for (int j = 0; j < rem; j += 2) {
            int idx = j + half;
            int sj = __shfl_sync(0xffffffffu, s, (idx < rem) ? idx : 0);
            if (idx < rem) {
                uint4 u = hbase[(size_t)sj * 16 + hl];
                float2 f0 = __half22float2(*(__half2*)&u.x);
                float2 f1 = __half22float2(*(__half2*)&u.y);
                float2 f2 = __half22float2(*(__half2*)&u.z);
                float2 f3 = __half22float2(*(__half2*)&u.w);
                acc[0] += f0.x; acc[1] += f0.y; acc[2] += f1.x; acc[3] += f1.y;
                acc[4] += f2.x; acc[5] += f2.y; acc[6] += f3.x; acc[7] += f3.y;
            }
        }
    }
    // cross-half reduction: lane l += lane l+16
#pragma unroll
    for (int c = 0; c < 8; c++)
        acc[c] += __shfl_down_sync(0xffffffffu, acc[c], 16);

    if (half == 0) {
        float inv = 1.0f / fmaxf((float)deg, 1.0f);
        __half2 p0 = __float22half2_rn(make_float2(acc[0] * inv, acc[1] * inv));
        __half2 p1 = __float22half2_rn(make_float2(acc[2] * inv, acc[3] * inv));
        __half2 p2 = __float22half2_rn(make_float2(acc[4] * inv, acc[5] * inv));
        __half2 p3 = __float22half2_rn(make_float2(acc[6] * inv, acc[7] * inv));
        uint4 o;
        o.x = *(uint32_t*)&p0;  o.y = *(uint32_t*)&p1;
        o.z = *(uint32_t*)&p2;  o.w = *(uint32_t*)&p3;
        *((uint4*)(g_neigh16 + (size_t)gwarp * DD) + hl) = o;
    }
}

// ---------------------------------------------------------------- FP16 mma.sync GEMM
// rst = relu([h | neigh] @ W + bias); BN column sums fused (fp32 exact).
#define STRD16 40                     // halves per smem row (32 + 8 pad)
#define TILE16 (128 * STRD16)
__global__ __launch_bounds__(256, 2) void k_gemm(const float* __restrict__ bias) {
    extern __shared__ __half sm16[];
    float* cs = (float*)(sm16 + 4 * TILE16);
    float* cq = cs + 128;

    int tid = threadIdx.x;
    int wid = tid >> 5, lane = tid & 31;
    int g = lane >> 2, t = lane & 3;
    int warpM = wid >> 2, warpN = wid & 3;
    int m0 = blockIdx.x * 128;

    if (tid < 128) { cs[tid] = 0.f; cq[tid] = 0.f; }

    uint32_t sb = smem_u32(sm16);

    auto issue = [&](int kk, int buf) {
        uint32_t abase = sb + (uint32_t)(buf * TILE16) * 2u;
#pragma unroll
        for (int i = 0; i < 2; i++) {
            int slot = tid + i * 256;           // 512 slots
            int row = slot >> 2, seg = slot & 3;
            int gm = m0 + row;
            const __half* gp = (kk < 4)
                ? (g_h16 + (size_t)gm * DD + kk * 32 + seg * 8)
                : (g_neigh16 + (size_t)gm * DD + (kk - 4) * 32 + seg * 8);
            cp16(abase + row * (STRD16 * 2) + seg * 16, gp, gm < NN);
        }
        uint32_t bbase = sb + (uint32_t)((2 + buf) * TILE16) * 2u;
#pragma unroll
        for (int i = 0; i < 2; i++) {
            int slot = tid + i * 256;
            int row = slot >> 2, seg = slot & 3;
            cp16(bbase + row * (STRD16 * 2) + seg * 16,
                 g_Wt16 + (size_t)row * 256 + kk * 32 + seg * 8, true);
        }
        CP_COMMIT();
    };

    issue(0, 0);

    float acc[4][4][4];
#pragma unroll
    for (int a = 0; a < 4; a++)
#pragma unroll
        for (int b = 0; b < 4; b++)
#pragma unroll
            for (int c = 0; c < 4; c++) acc[a][b][c] = 0.f;

    CP_WAIT0();
    __syncthreads();

    for (int kk = 0; kk < 8; kk++) {
        int buf = kk & 1;
        if (kk < 7) issue(kk + 1, buf ^ 1);
        const __half* A = sm16 + buf * TILE16;
        const __half* B = sm16 + (2 + buf) * TILE16;
#pragma unroll
        for (int ks = 0; ks < 2; ks++) {
            int kb = ks * 16;
            uint32_t bf[4][2];
#pragma unroll
            for (int nf = 0; nf < 4; nf++) {
                int n = warpN * 32 + nf * 8 + g;
                bf[nf][0] = *(const uint32_t*)&B[n * STRD16 + kb + 2 * t];
                bf[nf][1] = *(const uint32_t*)&B[n * STRD16 + kb + 2 * t + 8];
            }
#pragma unroll
            for (int mf = 0; mf < 4; mf++) {
                int m = warpM * 64 + mf * 16;
                uint32_t a0 = *(const uint32_t*)&A[(m + g) * STRD16 + kb + 2 * t];
                uint32_t a1 = *(const uint32_t*)&A[(m + g + 8) * STRD16 + kb + 2 * t];
                uint32_t a2 = *(const uint32_t*)&A[(m + g) * STRD16 + kb + 2 * t + 8];
                uint32_t a3 = *(const uint32_t*)&A[(m + g + 8) * STRD16 + kb + 2 * t + 8];
#pragma unroll
                for (int nf = 0; nf < 4; nf++)
                    mma16(acc[mf][nf], a0, a1, a2, a3, bf[nf][0], bf[nf][1]);
            }
        }
        CP_WAIT0();
        __syncthreads();
    }

    // ---- epilogue: bias + relu, fp16 store, per-block BN partials (fp32 exact) ----
#pragma unroll
    for (int nf = 0; nf < 4; nf++) {
        int col = warpN * 32 + nf * 8 + 2 * t;
        float2 bv = *(const float2*)(bias + col);
        float s0 = 0.f, s1 = 0.f, q0 = 0.f, q1 = 0.f;
#pragma unroll
        for (int mf = 0; mf < 4; mf++) {
#pragma unroll
            for (int hh = 0; hh < 2; hh++) {
                int row = m0 + warpM * 64 + mf * 16 + g + hh * 8;
                float v0 = fmaxf(acc[mf][nf][hh * 2 + 0] + bv.x, 0.f);
                float v1 = fmaxf(acc[mf][nf][hh * 2 + 1] + bv.y, 0.f);
                if (row < NN) {
                    __half2 p = __float22half2_rn(make_float2(v0, v1));
                    *(__half2*)(g_rst16 + (size_t)row * DD + col) = p;
                    s0 += v0; q0 += v0 * v0;
                    s1 += v1; q1 += v1 * v1;
                }
            }
        }
        atomicAdd(&cs[col], s0);     atomicAdd(&cs[col + 1], s1);
        atomicAdd(&cq[col], q0);     atomicAdd(&cq[col + 1], q1);
    }
    __syncthreads();
    if (tid < 128) {
        atomicAdd(&g_colsum[tid], cs[tid]);
        atomicAdd(&g_colsumsq[tid], cq[tid]);
    }
}

// ---------------------------------------------------------------- fold BN params
__global__ void k_stats(const float* __restrict__ gamma, const float* __restrict__ beta) {
    int j = threadIdx.x;
    if (j >= DD) return;
    float mean = g_colsum[j] / (float)NN;
    float var = g_colsumsq[j] / (float)NN - mean * mean;
    float rs = rsqrtf(var + BN_EPS);
    float sc = rs * gamma[j];
    g_scale[j] = sc;
    g_shift[j] = beta[j] - mean * sc;
}

// ---------------------------------------------------------------- normalize + residual
__global__ void k_final(const float* __restrict__ h, float* __restrict__ out) {
    int i4 = blockIdx.x * blockDim.x + threadIdx.x;
    const int TOT = NN * DD / 4;
    if (i4 >= TOT) return;
    int c4 = i4 & 31;
    uint2 u = ((const uint2*)g_rst16)[i4];
    float2 r0 = __half22float2(*(__half2*)&u.x);
    float2 r1 = __half22float2(*(__half2*)&u.y);
    float4 hv = ((const float4*)h)[i4];
    float4 sc = ((const float4*)g_scale)[c4];
    float4 sh = ((const float4*)g_shift)[c4];
    float4 o;
    o.x = hv.x + r0.x * sc.x + sh.x;
    o.y = hv.y + r0.y * sc.y + sh.y;
    o.z = hv.z + r1.x * sc.z + sh.z;
    o.w = hv.w + r1.y * sc.w + sh.w;
    ((float4*)out)[i4] = o;
}

// ---------------------------------------------------------------- launch
extern "C" void kernel_launch(void* const* d_in, const int* in_sizes, int n_in,
                              void* d_out, int out_size) {
    const float* h     = (const float*)d_in[0];
    const int*   src   = (const int*)d_in[1];
    const int*   dst   = (const int*)d_in[2];
    const float* Ws    = (const float*)d_in[3];
    const float* Wn    = (const float*)d_in[4];
    const float* bias  = (const float*)d_in[5];
    const float* gamma = (const float*)d_in[6];
    const float* beta  = (const float*)d_in[7];
    float* out = (float*)d_out;

    const int GEMM_SMEM = 4 * TILE16 * 2 + 256 * 4;

    static cudaStream_t s2 = nullptr;
    static cudaEvent_t evFork = nullptr, evJoin = nullptr;
    if (!s2) {
        cudaFuncSetAttribute(k_gemm, cudaFuncAttributeMaxDynamicSharedMemorySize, GEMM_SMEM);
        cudaStreamCreateWithFlags(&s2, cudaStreamNonBlocking);
        cudaEventCreateWithFlags(&evFork, cudaEventDisableTiming);
        cudaEventCreateWithFlags(&evJoin, cudaEventDisableTiming);
    }

    // fork: h16 + wt on s2, overlapped with CSR build on stream 0
    cudaEventRecord(evFork, 0);
    cudaStreamWaitEvent(s2, evFork, 0);
    k_h16<<<(NN * DD / 8 + 255) / 256, 256, 0, s2>>>(h);
    k_wt<<<(128 * 256 + 255) / 256, 256, 0, s2>>>(Ws, Wn);
    cudaEventRecord(evJoin, s2);

    k_zero<<<(NN + 255) / 256, 256>>>();
    k_hist<<<(EE / 4 + 255) / 256, 256>>>(dst);
    k_scan_blk<<<NBLK, 1024>>>();
    k_scan_top<<<1, 128>>>();
    k_scan_add<<<NBLK, 1024>>>();
    k_scatter<<<(EE / 4 + 255) / 256, 256>>>(src, dst);

    // join: aggregate needs g_h16, gemm needs g_Wt16
    cudaStreamWaitEvent(0, evJoin, 0);
    k_aggregate<<<(NN * 32 + 255) / 256, 256>>>();
    k_gemm<<<(NN + 127) / 128, 256, GEMM_SMEM>>>(bias);
    k_stats<<<1, 128>>>(gamma, beta);
    k_final<<<(NN * DD / 4 + 255) / 256, 256>>>(h, out);
}

// round 11
// speedup vs baseline: 1.1673x; 1.1673x over previous
#include <cuda_runtime.h>
#include <cuda_fp16.h>
#include <cstdint>

#define NN 100000
#define EE 3200000
#define DD 128
#define BN_EPS 1e-5f
#define NBLK 98   // ceil(NN/1024)

// ---- scratch (device globals) ----
__device__ int    g_count[NN];
__device__ int    g_offset[NN];
__device__ int    g_blksum[NBLK];
__device__ int    g_blkoff[NBLK];
__device__ int    g_rank[EE];
__device__ int    g_edge_src[EE];
__device__ __half g_h16[(size_t)NN * DD];
__device__ __half g_neigh16[(size_t)NN * DD];
__device__ __half g_rst16[(size_t)NN * DD];
__device__ __half g_Wt16[128 * 256];   // [n][k] fp16 W^T over [W_self; W_neigh]
__device__ float  g_colsum[DD];
__device__ float  g_colsumsq[DD];

// ================= helpers =================
__device__ __forceinline__ uint32_t smem_u32(const void* p) {
    uint32_t a;
    asm("{ .reg .u64 t; cvta.to.shared.u64 t, %1; cvt.u32.u64 %0, t; }" : "=r"(a) : "l"(p));
    return a;
}
__device__ __forceinline__ void cp16(uint32_t saddr, const void* gaddr, bool valid) {
    asm volatile("cp.async.cg.shared.global [%0], [%1], 16, %2;"
                 :: "r"(saddr), "l"(gaddr), "r"(valid ? 16u : 0u) : "memory");
}
#define CP_COMMIT() asm volatile("cp.async.commit_group;" ::: "memory")
#define CP_WAIT0()  asm volatile("cp.async.wait_group 0;" ::: "memory")

__device__ __forceinline__ void mma16(float* d, uint32_t a0, uint32_t a1, uint32_t a2,
                                      uint32_t a3, uint32_t b0, uint32_t b1) {
    asm volatile(
        "mma.sync.aligned.m16n8k16.row.col.f32.f16.f16.f32 "
        "{%0,%1,%2,%3}, {%4,%5,%6,%7}, {%8,%9}, {%0,%1,%2,%3};"
        : "+f"(d[0]), "+f"(d[1]), "+f"(d[2]), "+f"(d[3])
        : "r"(a0), "r"(a1), "r"(a2), "r"(a3), "r"(b0), "r"(b1));
}

// ---------------------------------------------------------------- zero
__global__ void k_zero() {
    int i = blockIdx.x * blockDim.x + threadIdx.x;
    if (i < NN) g_count[i] = 0;
    if (i < DD) { g_colsum[i] = 0.f; g_colsumsq[i] = 0.f; }
}

// ---------------------------------------------------------------- h -> fp16 copy
__global__ void k_h16(const float* __restrict__ h) {
    int i = blockIdx.x * blockDim.x + threadIdx.x;   // one per 8 floats
    const int TOT = NN * DD / 8;
    if (i >= TOT) return;
    float4 a = ((const float4*)h)[2 * i];
    float4 b = ((const float4*)h)[2 * i + 1];
    __half2 r[4];
    r[0] = __float22half2_rn(make_float2(a.x, a.y));
    r[1] = __float22half2_rn(make_float2(a.z, a.w));
    r[2] = __float22half2_rn(make_float2(b.x, b.y));
    r[3] = __float22half2_rn(make_float2(b.z, b.w));
    ((uint4*)g_h16)[i] = *(uint4*)r;
}

// ---------------------------------------------------------------- W transpose + fp16 round
__global__ void k_wt(const float* __restrict__ Ws, const float* __restrict__ Wn) {
    int i = blockIdx.x * blockDim.x + threadIdx.x;
    if (i >= 128 * 256) return;
    int n = i >> 8, k = i & 255;
    float v = (k < 128) ? Ws[(size_t)k * DD + n] : Wn[(size_t)(k - 128) * DD + n];
    g_Wt16[i] = __float2half_rn(v);
}

// ---------------------------------------------------------------- degree histogram + edge rank (4-wide)
__global__ void k_hist(const int* __restrict__ dst) {
    int e4 = blockIdx.x * blockDim.x + threadIdx.x;
    if (e4 >= EE / 4) return;
    int4 d = ((const int4*)dst)[e4];
    int4 r;
    r.x = atomicAdd(&g_count[d.x], 1);
    r.y = atomicAdd(&g_count[d.y], 1);
    r.z = atomicAdd(&g_count[d.z], 1);
    r.w = atomicAdd(&g_count[d.w], 1);
    ((int4*)g_rank)[e4] = r;
}

// ---------------------------------------------------------------- scan phase 1: per-block
__global__ void k_scan_blk() {
    __shared__ int wsum[32];
    int t = threadIdx.x;
    int i = blockIdx.x * 1024 + t;
    int lane = t & 31, wid = t >> 5;
    int v = (i < NN) ? g_count[i] : 0;
    int x = v;
#pragma unroll
    for (int o = 1; o < 32; o <<= 1) {
        int y = __shfl_up_sync(0xffffffffu, x, o);
        if (lane >= o) x += y;
    }
    if (lane == 31) wsum[wid] = x;
    __syncthreads();
    if (wid == 0) {
        int s = wsum[lane];
#pragma unroll
        for (int o = 1; o < 32; o <<= 1) {
            int y = __shfl_up_sync(0xffffffffu, s, o);
            if (lane >= o) s += y;
        }
        wsum[lane] = s;
    }
    __syncthreads();
    int warpoff = (wid == 0) ? 0 : wsum[wid - 1];
    if (i < NN) g_offset[i] = warpoff + x - v;
    if (t == 1023) g_blksum[blockIdx.x] = warpoff + x;
}

// ---------------------------------------------------------------- scan phase 2: block totals
__global__ void k_scan_top() {
    __shared__ int wsum[4];
    int t = threadIdx.x;            // 128 threads
    int lane = t & 31, wid = t >> 5;
    int v = (t < NBLK) ? g_blksum[t] : 0;
    int x = v;
#pragma unroll
    for (int o = 1; o < 32; o <<= 1) {
        int y = __shfl_up_sync(0xffffffffu, x, o);
        if (lane >= o) x += y;
    }
    if (lane == 31) wsum[wid] = x;
    __syncthreads();
    int woff = 0;
    for (int w = 0; w < wid; w++) woff += wsum[w];
    if (t < NBLK) g_blkoff[t] = woff + x - v;
}

// ---------------------------------------------------------------- scatter into CSR (no atomics, 4-wide)
// offset = g_offset[d] (block-local prefix) + g_blkoff[d>>10] (block base)
__global__ void k_scatter(const int* __restrict__ src,
                          const int* __restrict__ dst) {
    int e4 = blockIdx.x * blockDim.x + threadIdx.x;
    if (e4 >= EE / 4) return;
    int4 d = ((const int4*)dst)[e4];
    int4 s = ((const int4*)src)[e4];
    int4 r = ((const int4*)g_rank)[e4];
    g_edge_src[g_offset[d.x] + g_blkoff[d.x >> 10] + r.x] = s.x;
    g_edge_src[g_offset[d.y] + g_blkoff[d.y >> 10] + r.y] = s.y;
    g_edge_src[g_offset[d.z] + g_blkoff[d.z >> 10] + r.z] = s.z;
    g_edge_src[g_offset[d.w] + g_blkoff[d.w >> 10] + r.w] = s.w;
}

// ---------------------------------------------------------------- segment mean (1 warp / node, fp16 gather)
// Each lane owns 4 columns: one uint2 (4 halves) per edge row. Output fp16.
__global__ void k_aggregate() {
    int gwarp = (blockIdx.x * blockDim.x + threadIdx.x) >> 5;
    if (gwarp >= NN) return;
    int lane = threadIdx.x & 31;
    int start = g_offset[gwarp] + g_blkoff[gwarp >> 10];
    int deg = g_count[gwarp];

    float accA[4] = {0, 0, 0, 0};
    float accB[4] = {0, 0, 0, 0};

    int i = 0;
    for (; i + 32 <= deg; i += 32) {
        int s = g_edge_src[start + i + lane];
#pragma unroll
        for (int j = 0; j < 32; j += 2) {
            int s0 = __shfl_sync(0xffffffffu, s, j);
            int s1 = __shfl_sync(0xffffffffu, s, j + 1);
            uint2 u0 = *((const uint2*)(g_h16 + (size_t)s0 * DD) + lane);
            uint2 u1 = *((const uint2*)(g_h16 + (size_t)s1 * DD) + lane);
            {
                float2 f0 = __half22float2(*(__half2*)&u0.x);
                float2 f1 = __half22float2(*(__half2*)&u0.y);
                accA[0] += f0.x; accA[1] += f0.y; accA[2] += f1.x; accA[3] += f1.y;
            }
            {
                float2 f0 = __half22float2(*(__half2*)&u1.x);
                float2 f1 = __half22float2(*(__half2*)&u1.y);
                accB[0] += f0.x; accB[1] += f0.y; accB[2] += f1.x; accB[3] += f1.y;
            }
        }
    }
    {
        int rem = deg - i;
        int s = (lane < rem) ? g_edge_src[start + i + lane] : 0;
        for (int j = 0; j < rem; j++) {
            int sj = __shfl_sync(0xffffffffu, s, j);
            uint2 u = *((const uint2*)(g_h16 + (size_t)sj * DD) + lane);
            float2 f0 = __half22float2(*(__half2*)&u.x);
            float2 f1 = __half22float2(*(__half2*)&u.y);
            accA[0] += f0.x; accA[1] += f0.y; accA[2] += f1.x; accA[3] += f1.y;
        }
    }
    float inv = 1.0f / fmaxf((float)deg, 1.0f);
    __half2 p0 = __float22half2_rn(make_float2((accA[0] + accB[0]) * inv,
                                               (accA[1] + accB[1]) * inv));
    __half2 p1 = __float22half2_rn(make_float2((accA[2] + accB[2]) * inv,
                                               (accA[3] + accB[3]) * inv));
    uint2 o;
    o.x = *(uint32_t*)&p0;
    o.y = *(uint32_t*)&p1;
    *((uint2*)(g_neigh16 + (size_t)gwarp * DD) + lane) = o;
}

// ---------------------------------------------------------------- FP16 mma.sync GEMM
// rst = relu([h | neigh] @ W + bias); BN column sums fused (fp32 exact).
#define STRD16 40                     // halves per smem row (32 + 8 pad)
#define TILE16 (128 * STRD16)
__global__ __launch_bounds__(256, 2) void k_gemm(const float* __restrict__ bias) {
    extern __shared__ __half sm16[];
    float* cs = (float*)(sm16 + 4 * TILE16);
    float* cq = cs + 128;

    int tid = threadIdx.x;
    int wid = tid >> 5, lane = tid & 31;
    int g = lane >> 2, t = lane & 3;
    int warpM = wid >> 2, warpN = wid & 3;
    int m0 = blockIdx.x * 128;

    if (tid < 128) { cs[tid] = 0.f; cq[tid] = 0.f; }

    uint32_t sb = smem_u32(sm16);

    auto issue = [&](int kk, int buf) {
        uint32_t abase = sb + (uint32_t)(buf * TILE16) * 2u;
#pragma unroll
        for (int i = 0; i < 2; i++) {
            int slot = tid + i * 256;           // 512 slots
            int row = slot >> 2, seg = slot & 3;
            int gm = m0 + row;
            const __half* gp = (kk < 4)
                ? (g_h16 + (size_t)gm * DD + kk * 32 + seg * 8)
                : (g_neigh16 + (size_t)gm * DD + (kk - 4) * 32 + seg * 8);
            cp16(abase + row * (STRD16 * 2) + seg * 16, gp, gm < NN);
        }
        uint32_t bbase = sb + (uint32_t)((2 + buf) * TILE16) * 2u;
#pragma unroll
        for (int i = 0; i < 2; i++) {
            int slot = tid + i * 256;
            int row = slot >> 2, seg = slot & 3;
            cp16(bbase + row * (STRD16 * 2) + seg * 16,
                 g_Wt16 + (size_t)row * 256 + kk * 32 + seg * 8, true);
        }
        CP_COMMIT();
    };

    issue(0, 0);

    float acc[4][4][4];
#pragma unroll
    for (int a = 0; a < 4; a++)
#pragma unroll
        for (int b = 0; b < 4; b++)
#pragma unroll
            for (int c = 0; c < 4; c++) acc[a][b][c] = 0.f;

    CP_WAIT0();
    __syncthreads();

    for (int kk = 0; kk < 8; kk++) {
        int buf = kk & 1;
        if (kk < 7) issue(kk + 1, buf ^ 1);
        const __half* A = sm16 + buf * TILE16;
        const __half* B = sm16 + (2 + buf) * TILE16;
#pragma unroll
        for (int ks = 0; ks < 2; ks++) {
            int kb = ks * 16;
            uint32_t bf[4][2];
#pragma unroll
            for (int nf = 0; nf < 4; nf++) {
                int n = warpN * 32 + nf * 8 + g;
                bf[nf][0] = *(const uint32_t*)&B[n * STRD16 + kb + 2 * t];
                bf[nf][1] = *(const uint32_t*)&B[n * STRD16 + kb + 2 * t + 8];
            }
#pragma unroll
            for (int mf = 0; mf < 4; mf++) {
                int m = warpM * 64 + mf * 16;
                uint32_t a0 = *(const uint32_t*)&A[(m + g) * STRD16 + kb + 2 * t];
                uint32_t a1 = *(const uint32_t*)&A[(m + g + 8) * STRD16 + kb + 2 * t];
                uint32_t a2 = *(const uint32_t*)&A[(m + g) * STRD16 + kb + 2 * t + 8];
                uint32_t a3 = *(const uint32_t*)&A[(m + g + 8) * STRD16 + kb + 2 * t + 8];
#pragma unroll
                for (int nf = 0; nf < 4; nf++)
                    mma16(acc[mf][nf], a0, a1, a2, a3, bf[nf][0], bf[nf][1]);
            }
        }
        CP_WAIT0();
        __syncthreads();
    }

    // ---- epilogue: bias + relu, fp16 store, per-block BN partials (fp32 exact) ----
#pragma unroll
    for (int nf = 0; nf < 4; nf++) {
        int col = warpN * 32 + nf * 8 + 2 * t;
        float2 bv = *(const float2*)(bias + col);
        float s0 = 0.f, s1 = 0.f, q0 = 0.f, q1 = 0.f;
#pragma unroll
        for (int mf = 0; mf < 4; mf++) {
#pragma unroll
            for (int hh = 0; hh < 2; hh++) {
                int row = m0 + warpM * 64 + mf * 16 + g + hh * 8;
                float v0 = fmaxf(acc[mf][nf][hh * 2 + 0] + bv.x, 0.f);
                float v1 = fmaxf(acc[mf][nf][hh * 2 + 1] + bv.y, 0.f);
                if (row < NN) {
                    __half2 p = __float22half2_rn(make_float2(v0, v1));
                    *(__half2*)(g_rst16 + (size_t)row * DD + col) = p;
                    s0 += v0; q0 += v0 * v0;
                    s1 += v1; q1 += v1 * v1;
                }
            }
        }
        atomicAdd(&cs[col], s0);     atomicAdd(&cs[col + 1], s1);
        atomicAdd(&cq[col], q0);     atomicAdd(&cq[col + 1], q1);
    }
    __syncthreads();
    if (tid < 128) {
        atomicAdd(&g_colsum[tid], cs[tid]);
        atomicAdd(&g_colsumsq[tid], cq[tid]);
    }
}

// ---------------------------------------------------------------- normalize + residual (BN fold inline)
__global__ __launch_bounds__(256) void k_final(const float* __restrict__ h,
                                               const float* __restrict__ gamma,
                                               const float* __restrict__ beta,
                                               float* __restrict__ out) {
    __shared__ float s_scale[DD];
    __shared__ float s_shift[DD];
    if (threadIdx.x < DD) {
        int j = threadIdx.x;
        float mean = g_colsum[j] / (float)NN;
        float var = g_colsumsq[j] / (float)NN - mean * mean;
        float rs = rsqrtf(var + BN_EPS);
        float sc = rs * gamma[j];
        s_scale[j] = sc;
        s_shift[j] = beta[j] - mean * sc;
    }
    __syncthreads();

    int i4 = blockIdx.x * blockDim.x + threadIdx.x;
    const int TOT = NN * DD / 4;
    if (i4 >= TOT) return;
    int c4 = i4 & 31;
    uint2 u = ((const uint2*)g_rst16)[i4];
    float2 r0 = __half22float2(*(__half2*)&u.x);
    float2 r1 = __half22float2(*(__half2*)&u.y);
    float4 hv = ((const float4*)h)[i4];
    float4 sc = *((const float4*)s_scale + c4);
    float4 sh = *((const float4*)s_shift + c4);
    float4 o;
    o.x = hv.x + r0.x * sc.x + sh.x;
    o.y = hv.y + r0.y * sc.y + sh.y;
    o.z = hv.z + r1.x * sc.z + sh.z;
    o.w = hv.w + r1.y * sc.w + sh.w;
    ((float4*)out)[i4] = o;
}

// ---------------------------------------------------------------- launch
extern "C" void kernel_launch(void* const* d_in, const int* in_sizes, int n_in,
                              void* d_out, int out_size) {
    const float* h     = (const float*)d_in[0];
    const int*   src   = (const int*)d_in[1];
    const int*   dst   = (const int*)d_in[2];
    const float* Ws    = (const float*)d_in[3];
    const float* Wn    = (const float*)d_in[4];
    const float* bias  = (const float*)d_in[5];
    const float* gamma = (const float*)d_in[6];
    const float* beta  = (const float*)d_in[7];
    float* out = (float*)d_out;

    const int GEMM_SMEM = 4 * TILE16 * 2 + 256 * 4;
    static bool attr_set = false;
    if (!attr_set) {
        cudaFuncSetAttribute(k_gemm, cudaFuncAttributeMaxDynamicSharedMemorySize, GEMM_SMEM);
        attr_set = true;
    }

    k_zero<<<(NN + 255) / 256, 256>>>();
    k_h16<<<(NN * DD / 8 + 255) / 256, 256>>>(h);
    k_wt<<<(128 * 256 + 255) / 256, 256>>>(Ws, Wn);
    k_hist<<<(EE / 4 + 255) / 256, 256>>>(dst);
    k_scan_blk<<<NBLK, 1024>>>();
    k_scan_top<<<1, 128>>>();
    k_scatter<<<(EE / 4 + 255) / 256, 256>>>(src, dst);
    k_aggregate<<<(NN * 32 + 255) / 256, 256>>>();
    k_gemm<<<(NN + 127) / 128, 256, GEMM_SMEM>>>(bias);
    k_final<<<(NN * DD / 4 + 255) / 256, 256>>>(h, gamma, beta, out);
}

// round 12
// speedup vs baseline: 1.1917x; 1.0208x over previous
#include <cuda_runtime.h>
#include <cuda_fp16.h>
#include <cstdint>

#define NN 100000
#define EE 3200000
#define DD 128
#define BN_EPS 1e-5f
#define NBLK 98   // ceil(NN/1024)

#define HIST_BLOCKS (EE / 4 / 256)            // 3125
#define H16_BLOCKS  (NN * DD / 8 / 256 + 1)   // 6251
#define WT_BLOCKS   (128 * 256 / 256)         // 128
#define FUSED_BLOCKS (HIST_BLOCKS + H16_BLOCKS + WT_BLOCKS)

// ---- scratch (device globals) ----
__device__ int    g_count[NN];
__device__ int    g_offset[NN];
__device__ int    g_blksum[NBLK];
__device__ int    g_blkoff[NBLK];
__device__ int    g_scan_ctr;
__device__ int    g_rank[EE];
__device__ int    g_edge_src[EE];
__device__ __half g_h16[(size_t)NN * DD];
__device__ __half g_neigh16[(size_t)NN * DD];
__device__ __half g_rst16[(size_t)NN * DD];
__device__ __half g_Wt16[128 * 256];   // [n][k] fp16 W^T over [W_self; W_neigh]
__device__ float  g_colsum[DD];
__device__ float  g_colsumsq[DD];

// ================= helpers =================
__device__ __forceinline__ uint32_t smem_u32(const void* p) {
    uint32_t a;
    asm("{ .reg .u64 t; cvta.to.shared.u64 t, %1; cvt.u32.u64 %0, t; }" : "=r"(a) : "l"(p));
    return a;
}
__device__ __forceinline__ void cp16(uint32_t saddr, const void* gaddr, bool valid) {
    asm volatile("cp.async.cg.shared.global [%0], [%1], 16, %2;"
                 :: "r"(saddr), "l"(gaddr), "r"(valid ? 16u : 0u) : "memory");
}
#define CP_COMMIT() asm volatile("cp.async.commit_group;" ::: "memory")
#define CP_WAIT0()  asm volatile("cp.async.wait_group 0;" ::: "memory")

__device__ __forceinline__ void mma16(float* d, uint32_t a0, uint32_t a1, uint32_t a2,
                                      uint32_t a3, uint32_t b0, uint32_t b1) {
    asm volatile(
        "mma.sync.aligned.m16n8k16.row.col.f32.f16.f16.f32 "
        "{%0,%1,%2,%3}, {%4,%5,%6,%7}, {%8,%9}, {%0,%1,%2,%3};"
        : "+f"(d[0]), "+f"(d[1]), "+f"(d[2]), "+f"(d[3])
        : "r"(a0), "r"(a1), "r"(a2), "r"(a3), "r"(b0), "r"(b1));
}

// ---------------------------------------------------------------- zero
__global__ void k_zero() {
    int i = blockIdx.x * blockDim.x + threadIdx.x;
    if (i < NN) g_count[i] = 0;
    if (i < DD) { g_colsum[i] = 0.f; g_colsumsq[i] = 0.f; }
    if (i == 0) g_scan_ctr = 0;
}

// ---------------------------------------------------------------- fused: hist | h->fp16 | W^T fp16
// blocks [0, HIST_BLOCKS): degree histogram + edge rank (4-wide)
// blocks [HIST_BLOCKS, HIST_BLOCKS+H16_BLOCKS): h -> fp16
// blocks [.., +WT_BLOCKS): W transpose + fp16 round
__global__ void k_hist_h16_wt(const int* __restrict__ dst,
                              const float* __restrict__ h,
                              const float* __restrict__ Ws,
                              const float* __restrict__ Wn) {
    int b = blockIdx.x;
    if (b < HIST_BLOCKS) {
        int e4 = b * 256 + threadIdx.x;
        if (e4 >= EE / 4) return;
        int4 d = ((const int4*)dst)[e4];
        int4 r;
        r.x = atomicAdd(&g_count[d.x], 1);
        r.y = atomicAdd(&g_count[d.y], 1);
        r.z = atomicAdd(&g_count[d.z], 1);
        r.w = atomicAdd(&g_count[d.w], 1);
        ((int4*)g_rank)[e4] = r;
    } else if (b < HIST_BLOCKS + H16_BLOCKS) {
        int i = (b - HIST_BLOCKS) * 256 + threadIdx.x;
        const int TOT = NN * DD / 8;
        if (i >= TOT) return;
        float4 a = ((const float4*)h)[2 * i];
        float4 bb = ((const float4*)h)[2 * i + 1];
        __half2 r[4];
        r[0] = __float22half2_rn(make_float2(a.x, a.y));
        r[1] = __float22half2_rn(make_float2(a.z, a.w));
        r[2] = __float22half2_rn(make_float2(bb.x, bb.y));
        r[3] = __float22half2_rn(make_float2(bb.z, bb.w));
        ((uint4*)g_h16)[i] = *(uint4*)r;
    } else {
        int i = (b - HIST_BLOCKS - H16_BLOCKS) * 256 + threadIdx.x;
        if (i >= 128 * 256) return;
        int n = i >> 8, k = i & 255;
        float v = (k < 128) ? Ws[(size_t)k * DD + n] : Wn[(size_t)(k - 128) * DD + n];
        g_Wt16[i] = __float2half_rn(v);
    }
}

// ---------------------------------------------------------------- scan (block prefix + last-block top scan)
__global__ void k_scan_blk() {
    __shared__ int wsum[32];
    __shared__ bool s_last;
    int t = threadIdx.x;
    int i = blockIdx.x * 1024 + t;
    int lane = t & 31, wid = t >> 5;
    int v = (i < NN) ? g_count[i] : 0;
    int x = v;
#pragma unroll
    for (int o = 1; o < 32; o <<= 1) {
        int y = __shfl_up_sync(0xffffffffu, x, o);
        if (lane >= o) x += y;
    }
    if (lane == 31) wsum[wid] = x;
    __syncthreads();
    if (wid == 0) {
        int s = wsum[lane];
#pragma unroll
        for (int o = 1; o < 32; o <<= 1) {
            int y = __shfl_up_sync(0xffffffffu, s, o);
            if (lane >= o) s += y;
        }
        wsum[lane] = s;
    }
    __syncthreads();
    int warpoff = (wid == 0) ? 0 : wsum[wid - 1];
    if (i < NN) g_offset[i] = warpoff + x - v;
    if (t == 1023) g_blksum[blockIdx.x] = warpoff + x;

    // last block to finish scans the 98 block totals
    __syncthreads();
    if (t == 0) {
        __threadfence();
        s_last = (atomicAdd(&g_scan_ctr, 1) == gridDim.x - 1);
    }
    __syncthreads();
    if (s_last) {
        __threadfence();
        if (t < 128) {
            __shared__ int w2[4];
            int vv = (t < NBLK) ? g_blksum[t] : 0;
            int xx = vv;
#pragma unroll
            for (int o = 1; o < 32; o <<= 1) {
                int y = __shfl_up_sync(0xffffffffu, xx, o);
                if (lane >= o) xx += y;
            }
            if (lane == 31) w2[wid] = xx;
            __syncwarp();
            // only warps 0..3 participate (t<128)
            __syncthreads();
            int woff = 0;
            for (int w = 0; w < wid; w++) woff += w2[w];
            if (t < NBLK) g_blkoff[t] = woff + xx - vv;
        } else {
            __syncthreads();
        }
    }
}

// ---------------------------------------------------------------- scatter into CSR (no atomics, 4-wide)
__global__ void k_scatter(const int* __restrict__ src,
                          const int* __restrict__ dst) {
    int e4 = blockIdx.x * blockDim.x + threadIdx.x;
    if (e4 >= EE / 4) return;
    int4 d = ((const int4*)dst)[e4];
    int4 s = ((const int4*)src)[e4];
    int4 r = ((const int4*)g_rank)[e4];
    g_edge_src[g_offset[d.x] + g_blkoff[d.x >> 10] + r.x] = s.x;
    g_edge_src[g_offset[d.y] + g_blkoff[d.y >> 10] + r.y] = s.y;
    g_edge_src[g_offset[d.z] + g_blkoff[d.z >> 10] + r.z] = s.z;
    g_edge_src[g_offset[d.w] + g_blkoff[d.w >> 10] + r.w] = s.w;
}

// ---------------------------------------------------------------- segment mean (1 warp / node, fp16 gather)
__global__ void k_aggregate() {
    int gwarp = (blockIdx.x * blockDim.x + threadIdx.x) >> 5;
    if (gwarp >= NN) return;
    int lane = threadIdx.x & 31;
    int start = g_offset[gwarp] + g_blkoff[gwarp >> 10];
    int deg = g_count[gwarp];

    float accA[4] = {0, 0, 0, 0};
    float accB[4] = {0, 0, 0, 0};

    int i = 0;
    for (; i + 32 <= deg; i += 32) {
        int s = g_edge_src[start + i + lane];
#pragma unroll
        for (int j = 0; j < 32; j += 2) {
            int s0 = __shfl_sync(0xffffffffu, s, j);
            int s1 = __shfl_sync(0xffffffffu, s, j + 1);
            uint2 u0 = *((const uint2*)(g_h16 + (size_t)s0 * DD) + lane);
            uint2 u1 = *((const uint2*)(g_h16 + (size_t)s1 * DD) + lane);
            {
                float2 f0 = __half22float2(*(__half2*)&u0.x);
                float2 f1 = __half22float2(*(__half2*)&u0.y);
                accA[0] += f0.x; accA[1] += f0.y; accA[2] += f1.x; accA[3] += f1.y;
            }
            {
                float2 f0 = __half22float2(*(__half2*)&u1.x);
                float2 f1 = __half22float2(*(__half2*)&u1.y);
                accB[0] += f0.x; accB[1] += f0.y; accB[2] += f1.x; accB[3] += f1.y;
            }
        }
    }
    {
        int rem = deg - i;
        int s = (lane < rem) ? g_edge_src[start + i + lane] : 0;
        for (int j = 0; j < rem; j++) {
            int sj = __shfl_sync(0xffffffffu, s, j);
            uint2 u = *((const uint2*)(g_h16 + (size_t)sj * DD) + lane);
            float2 f0 = __half22float2(*(__half2*)&u.x);
            float2 f1 = __half22float2(*(__half2*)&u.y);
            accA[0] += f0.x; accA[1] += f0.y; accA[2] += f1.x; accA[3] += f1.y;
        }
    }
    float inv = 1.0f / fmaxf((float)deg, 1.0f);
    __half2 p0 = __float22half2_rn(make_float2((accA[0] + accB[0]) * inv,
                                               (accA[1] + accB[1]) * inv));
    __half2 p1 = __float22half2_rn(make_float2((accA[2] + accB[2]) * inv,
                                               (accA[3] + accB[3]) * inv));
    uint2 o;
    o.x = *(uint32_t*)&p0;
    o.y = *(uint32_t*)&p1;
    *((uint2*)(g_neigh16 + (size_t)gwarp * DD) + lane) = o;
}

// ---------------------------------------------------------------- FP16 mma.sync GEMM
#define STRD16 40
#define TILE16 (128 * STRD16)
__global__ __launch_bounds__(256, 2) void k_gemm(const float* __restrict__ bias) {
    extern __shared__ __half sm16[];
    float* cs = (float*)(sm16 + 4 * TILE16);
    float* cq = cs + 128;

    int tid = threadIdx.x;
    int wid = tid >> 5, lane = tid & 31;
    int g = lane >> 2, t = lane & 3;
    int warpM = wid >> 2, warpN = wid & 3;
    int m0 = blockIdx.x * 128;

    if (tid < 128) { cs[tid] = 0.f; cq[tid] = 0.f; }

    uint32_t sb = smem_u32(sm16);

    auto issue = [&](int kk, int buf) {
        uint32_t abase = sb + (uint32_t)(buf * TILE16) * 2u;
#pragma unroll
        for (int i = 0; i < 2; i++) {
            int slot = tid + i * 256;
            int row = slot >> 2, seg = slot & 3;
            int gm = m0 + row;
            const __half* gp = (kk < 4)
                ? (g_h16 + (size_t)gm * DD + kk * 32 + seg * 8)
                : (g_neigh16 + (size_t)gm * DD + (kk - 4) * 32 + seg * 8);
            cp16(abase + row * (STRD16 * 2) + seg * 16, gp, gm < NN);
        }
        uint32_t bbase = sb + (uint32_t)((2 + buf) * TILE16) * 2u;
#pragma unroll
        for (int i = 0; i < 2; i++) {
            int slot = tid + i * 256;
            int row = slot >> 2, seg = slot & 3;
            cp16(bbase + row * (STRD16 * 2) + seg * 16,
                 g_Wt16 + (size_t)row * 256 + kk * 32 + seg * 8, true);
        }
        CP_COMMIT();
    };

    issue(0, 0);

    float acc[4][4][4];
#pragma unroll
    for (int a = 0; a < 4; a++)
#pragma unroll
        for (int b = 0; b < 4; b++)
#pragma unroll
            for (int c = 0; c < 4; c++) acc[a][b][c] = 0.f;

    CP_WAIT0();
    __syncthreads();

    for (int kk = 0; kk < 8; kk++) {
        int buf = kk & 1;
        if (kk < 7) issue(kk + 1, buf ^ 1);
        const __half* A = sm16 + buf * TILE16;
        const __half* B = sm16 + (2 + buf) * TILE16;
#pragma unroll
        for (int ks = 0; ks < 2; ks++) {
            int kb = ks * 16;
            uint32_t bf[4][2];
#pragma unroll
            for (int nf = 0; nf < 4; nf++) {
                int n = warpN * 32 + nf * 8 + g;
                bf[nf][0] = *(const uint32_t*)&B[n * STRD16 + kb + 2 * t];
                bf[nf][1] = *(const uint32_t*)&B[n * STRD16 + kb + 2 * t + 8];
            }
#pragma unroll
            for (int mf = 0; mf < 4; mf++) {
                int m = warpM * 64 + mf * 16;
                uint32_t a0 = *(const uint32_t*)&A[(m + g) * STRD16 + kb + 2 * t];
                uint32_t a1 = *(const uint32_t*)&A[(m + g + 8) * STRD16 + kb + 2 * t];
                uint32_t a2 = *(const uint32_t*)&A[(m + g) * STRD16 + kb + 2 * t + 8];
                uint32_t a3 = *(const uint32_t*)&A[(m + g + 8) * STRD16 + kb + 2 * t + 8];
#pragma unroll
                for (int nf = 0; nf < 4; nf++)
                    mma16(acc[mf][nf], a0, a1, a2, a3, bf[nf][0], bf[nf][1]);
            }
        }
        CP_WAIT0();
        __syncthreads();
    }

#pragma unroll
    for (int nf = 0; nf < 4; nf++) {
        int col = warpN * 32 + nf * 8 + 2 * t;
        float2 bv = *(const float2*)(bias + col);
        float s0 = 0.f, s1 = 0.f, q0 = 0.f, q1 = 0.f;
#pragma unroll
        for (int mf = 0; mf < 4; mf++) {
#pragma unroll
            for (int hh = 0; hh < 2; hh++) {
                int row = m0 + warpM * 64 + mf * 16 + g + hh * 8;
                float v0 = fmaxf(acc[mf][nf][hh * 2 + 0] + bv.x, 0.f);
                float v1 = fmaxf(acc[mf][nf][hh * 2 + 1] + bv.y, 0.f);
                if (row < NN) {
                    __half2 p = __float22half2_rn(make_float2(v0, v1));
                    *(__half2*)(g_rst16 + (size_t)row * DD + col) = p;
                    s0 += v0; q0 += v0 * v0;
                    s1 += v1; q1 += v1 * v1;
                }
            }
        }
        atomicAdd(&cs[col], s0);     atomicAdd(&cs[col + 1], s1);
        atomicAdd(&cq[col], q0);     atomicAdd(&cq[col + 1], q1);
    }
    __syncthreads();
    if (tid < 128) {
        atomicAdd(&g_colsum[tid], cs[tid]);
        atomicAdd(&g_colsumsq[tid], cq[tid]);
    }
}

// ---------------------------------------------------------------- normalize + residual (BN fold inline)
__global__ __launch_bounds__(256) void k_final(const float* __restrict__ h,
                                               const float* __restrict__ gamma,
                                               const float* __restrict__ beta,
                                               float* __restrict__ out) {
    __shared__ float s_scale[DD];
    __shared__ float s_shift[DD];
    if (threadIdx.x < DD) {
        int j = threadIdx.x;
        float mean = g_colsum[j] / (float)NN;
        float var = g_colsumsq[j] / (float)NN - mean * mean;
        float rs = rsqrtf(var + BN_EPS);
        float sc = rs * gamma[j];
        s_scale[j] = sc;
        s_shift[j] = beta[j] - mean * sc;
    }
    __syncthreads();

    int i4 = blockIdx.x * blockDim.x + threadIdx.x;
    const int TOT = NN * DD / 4;
    if (i4 >= TOT) return;
    int c4 = i4 & 31;
    uint2 u = ((const uint2*)g_rst16)[i4];
    float2 r0 = __half22float2(*(__half2*)&u.x);
    float2 r1 = __half22float2(*(__half2*)&u.y);
    float4 hv = ((const float4*)h)[i4];
    float4 sc = *((const float4*)s_scale + c4);
    float4 sh = *((const float4*)s_shift + c4);
    float4 o;
    o.x = hv.x + r0.x * sc.x + sh.x;
    o.y = hv.y + r0.y * sc.y + sh.y;
    o.z = hv.z + r1.x * sc.z + sh.z;
    o.w = hv.w + r1.y * sc.w + sh.w;
    ((float4*)out)[i4] = o;
}

// ---------------------------------------------------------------- launch
extern "C" void kernel_launch(void* const* d_in, const int* in_sizes, int n_in,
                              void* d_out, int out_size) {
    const float* h     = (const float*)d_in[0];
    const int*   src   = (const int*)d_in[1];
    const int*   dst   = (const int*)d_in[2];
    const float* Ws    = (const float*)d_in[3];
    const float* Wn    = (const float*)d_in[4];
    const float* bias  = (const float*)d_in[5];
    const float* gamma = (const float*)d_in[6];
    const float* beta  = (const float*)d_in[7];
    float* out = (float*)d_out;

    const int GEMM_SMEM = 4 * TILE16 * 2 + 256 * 4;
    static bool attr_set = false;
    if (!attr_set) {
        cudaFuncSetAttribute(k_gemm, cudaFuncAttributeMaxDynamicSharedMemorySize, GEMM_SMEM);
        attr_set = true;
    }

    k_zero<<<(NN + 255) / 256, 256>>>();
    k_hist_h16_wt<<<FUSED_BLOCKS, 256>>>(dst, h, Ws, Wn);
    k_scan_blk<<<NBLK, 1024>>>();
    k_scatter<<<(EE / 4 + 255) / 256, 256>>>(src, dst);
    k_aggregate<<<(NN * 32 + 255) / 256, 256>>>();
    k_gemm<<<(NN + 127) / 128, 256, GEMM_SMEM>>>(bias);
    k_final<<<(NN * DD / 4 + 255) / 256, 256>>>(h, gamma, beta, out);
}

// round 13
// speedup vs baseline: 1.2367x; 1.0378x over previous
#include <cuda_runtime.h>
#include <cuda_fp16.h>
#include <cstdint>

#define NN 100000
#define EE 3200000
#define DD 128
#define BN_EPS 1e-5f
#define CAP 64                         // slots per node (deg ~ Poisson(32))
#define MAXOVF (1 << 18)               // overflow capacity (pairs)

#define EDGE_BLOCKS (EE / 4 / 256)            // 3125
#define H16_BLOCKS  (NN * DD / 8 / 256 + 1)   // 6251
#define WT_BLOCKS   (128 * 256 / 256)         // 128
#define FUSED_BLOCKS (EDGE_BLOCKS + H16_BLOCKS + WT_BLOCKS)

// ---- scratch (device globals) ----
__device__ int    g_count[NN];
__device__ int    g_slots[(size_t)NN * CAP];   // src indices, slot r = rank r
__device__ int    g_ovf[2 * MAXOVF];           // (dst, src) pairs for rank >= CAP
__device__ int    g_ovf_ctr;
__device__ __half g_h16[(size_t)NN * DD];
__device__ __half g_neigh16[(size_t)NN * DD];
__device__ __half g_rst16[(size_t)NN * DD];
__device__ __half g_Wt16[128 * 256];           // [n][k] fp16 W^T over [W_self; W_neigh]
__device__ float  g_colsum[DD];
__device__ float  g_colsumsq[DD];

// ================= helpers =================
__device__ __forceinline__ uint32_t smem_u32(const void* p) {
    uint32_t a;
    asm("{ .reg .u64 t; cvta.to.shared.u64 t, %1; cvt.u32.u64 %0, t; }" : "=r"(a) : "l"(p));
    return a;
}
__device__ __forceinline__ void cp16(uint32_t saddr, const void* gaddr, bool valid) {
    asm volatile("cp.async.cg.shared.global [%0], [%1], 16, %2;"
                 :: "r"(saddr), "l"(gaddr), "r"(valid ? 16u : 0u) : "memory");
}
#define CP_COMMIT() asm volatile("cp.async.commit_group;" ::: "memory")
#define CP_WAIT0()  asm volatile("cp.async.wait_group 0;" ::: "memory")

__device__ __forceinline__ void mma16(float* d, uint32_t a0, uint32_t a1, uint32_t a2,
                                      uint32_t a3, uint32_t b0, uint32_t b1) {
    asm volatile(
        "mma.sync.aligned.m16n8k16.row.col.f32.f16.f16.f32 "
        "{%0,%1,%2,%3}, {%4,%5,%6,%7}, {%8,%9}, {%0,%1,%2,%3};"
        : "+f"(d[0]), "+f"(d[1]), "+f"(d[2]), "+f"(d[3])
        : "r"(a0), "r"(a1), "r"(a2), "r"(a3), "r"(b0), "r"(b1));
}

// ---------------------------------------------------------------- zero
__global__ void k_zero() {
    int i = blockIdx.x * blockDim.x + threadIdx.x;
    if (i < NN) g_count[i] = 0;
    if (i < DD) { g_colsum[i] = 0.f; g_colsumsq[i] = 0.f; }
    if (i == 0) g_ovf_ctr = 0;
}

// ---------------------------------------------------------------- fused: edge-slot build | h->fp16 | W^T fp16
__device__ __forceinline__ void place_edge(int d, int s) {
    int r = atomicAdd(&g_count[d], 1);
    if (r < CAP) {
        g_slots[(size_t)d * CAP + r] = s;
    } else {
        int idx = atomicAdd(&g_ovf_ctr, 1);
        if (idx < MAXOVF) { g_ovf[2 * idx] = d; g_ovf[2 * idx + 1] = s; }
    }
}
__global__ void k_build(const int* __restrict__ dst,
                        const int* __restrict__ src,
                        const float* __restrict__ h,
                        const float* __restrict__ Ws,
                        const float* __restrict__ Wn) {
    int b = blockIdx.x;
    if (b < EDGE_BLOCKS) {
        int e4 = b * 256 + threadIdx.x;
        if (e4 >= EE / 4) return;
        int4 d = ((const int4*)dst)[e4];
        int4 s = ((const int4*)src)[e4];
        place_edge(d.x, s.x);
        place_edge(d.y, s.y);
        place_edge(d.z, s.z);
        place_edge(d.w, s.w);
    } else if (b < EDGE_BLOCKS + H16_BLOCKS) {
        int i = (b - EDGE_BLOCKS) * 256 + threadIdx.x;
        const int TOT = NN * DD / 8;
        if (i >= TOT) return;
        float4 a = ((const float4*)h)[2 * i];
        float4 bb = ((const float4*)h)[2 * i + 1];
        __half2 r[4];
        r[0] = __float22half2_rn(make_float2(a.x, a.y));
        r[1] = __float22half2_rn(make_float2(a.z, a.w));
        r[2] = __float22half2_rn(make_float2(bb.x, bb.y));
        r[3] = __float22half2_rn(make_float2(bb.z, bb.w));
        ((uint4*)g_h16)[i] = *(uint4*)r;
    } else {
        int i = (b - EDGE_BLOCKS - H16_BLOCKS) * 256 + threadIdx.x;
        if (i >= 128 * 256) return;
        int n = i >> 8, k = i & 255;
        float v = (k < 128) ? Ws[(size_t)k * DD + n] : Wn[(size_t)(k - 128) * DD + n];
        g_Wt16[i] = __float2half_rn(v);
    }
}

// ---------------------------------------------------------------- segment mean (1 warp / node, fp16 gather)
// Each lane owns 4 columns: one uint2 (4 halves) per edge row. Output fp16.
__global__ void k_aggregate() {
    int gwarp = (blockIdx.x * blockDim.x + threadIdx.x) >> 5;
    if (gwarp >= NN) return;
    int lane = threadIdx.x & 31;
    int start = gwarp * CAP;
    int deg = g_count[gwarp];
    int main_n = (deg < CAP) ? deg : CAP;

    float accA[4] = {0, 0, 0, 0};
    float accB[4] = {0, 0, 0, 0};

    int i = 0;
    for (; i + 32 <= main_n; i += 32) {
        int s = g_slots[start + i + lane];
#pragma unroll
        for (int j = 0; j < 32; j += 2) {
            int s0 = __shfl_sync(0xffffffffu, s, j);
            int s1 = __shfl_sync(0xffffffffu, s, j + 1);
            uint2 u0 = *((const uint2*)(g_h16 + (size_t)s0 * DD) + lane);
            uint2 u1 = *((const uint2*)(g_h16 + (size_t)s1 * DD) + lane);
            {
                float2 f0 = __half22float2(*(__half2*)&u0.x);
                float2 f1 = __half22float2(*(__half2*)&u0.y);
                accA[0] += f0.x; accA[1] += f0.y; accA[2] += f1.x; accA[3] += f1.y;
            }
            {
                float2 f0 = __half22float2(*(__half2*)&u1.x);
                float2 f1 = __half22float2(*(__half2*)&u1.y);
                accB[0] += f0.x; accB[1] += f0.y; accB[2] += f1.x; accB[3] += f1.y;
            }
        }
    }
    {
        int rem = main_n - i;
        int s = (lane < rem) ? g_slots[start + i + lane] : 0;
        for (int j = 0; j < rem; j++) {
            int sj = __shfl_sync(0xffffffffu, s, j);
            uint2 u = *((const uint2*)(g_h16 + (size_t)sj * DD) + lane);
            float2 f0 = __half22float2(*(__half2*)&u.x);
            float2 f1 = __half22float2(*(__half2*)&u.y);
            accA[0] += f0.x; accA[1] += f0.y; accA[2] += f1.x; accA[3] += f1.y;
        }
    }
    // overflow edges (rank >= CAP): rare; scan append list for this dst
    if (deg > CAP) {
        int n = g_ovf_ctr;
        if (n > MAXOVF) n = MAXOVF;
        for (int o = 0; o < n; o++) {
            if (g_ovf[2 * o] == gwarp) {
                int sj = g_ovf[2 * o + 1];
                uint2 u = *((const uint2*)(g_h16 + (size_t)sj * DD) + lane);
                float2 f0 = __half22float2(*(__half2*)&u.x);
                float2 f1 = __half22float2(*(__half2*)&u.y);
                accA[0] += f0.x; accA[1] += f0.y; accA[2] += f1.x; accA[3] += f1.y;
            }
        }
    }
    float inv = 1.0f / fmaxf((float)deg, 1.0f);
    __half2 p0 = __float22half2_rn(make_float2((accA[0] + accB[0]) * inv,
                                               (accA[1] + accB[1]) * inv));
    __half2 p1 = __float22half2_rn(make_float2((accA[2] + accB[2]) * inv,
                                               (accA[3] + accB[3]) * inv));
    uint2 o;
    o.x = *(uint32_t*)&p0;
    o.y = *(uint32_t*)&p1;
    *((uint2*)(g_neigh16 + (size_t)gwarp * DD) + lane) = o;
}

// ---------------------------------------------------------------- FP16 mma.sync GEMM
#define STRD16 40
#define TILE16 (128 * STRD16)
__global__ __launch_bounds__(256, 2) void k_gemm(const float* __restrict__ bias) {
    extern __shared__ __half sm16[];
    float* cs = (float*)(sm16 + 4 * TILE16);
    float* cq = cs + 128;

    int tid = threadIdx.x;
    int wid = tid >> 5, lane = tid & 31;
    int g = lane >> 2, t = lane & 3;
    int warpM = wid >> 2, warpN = wid & 3;
    int m0 = blockIdx.x * 128;

    if (tid < 128) { cs[tid] = 0.f; cq[tid] = 0.f; }

    uint32_t sb = smem_u32(sm16);

    auto issue = [&](int kk, int buf) {
        uint32_t abase = sb + (uint32_t)(buf * TILE16) * 2u;
#pragma unroll
        for (int i = 0; i < 2; i++) {
            int slot = tid + i * 256;
            int row = slot >> 2, seg = slot & 3;
            int gm = m0 + row;
            const __half* gp = (kk < 4)
                ? (g_h16 + (size_t)gm * DD + kk * 32 + seg * 8)
                : (g_neigh16 + (size_t)gm * DD + (kk - 4) * 32 + seg * 8);
            cp16(abase + row * (STRD16 * 2) + seg * 16, gp, gm < NN);
        }
        uint32_t bbase = sb + (uint32_t)((2 + buf) * TILE16) * 2u;
#pragma unroll
        for (int i = 0; i < 2; i++) {
            int slot = tid + i * 256;
            int row = slot >> 2, seg = slot & 3;
            cp16(bbase + row * (STRD16 * 2) + seg * 16,
                 g_Wt16 + (size_t)row * 256 + kk * 32 + seg * 8, true);
        }
        CP_COMMIT();
    };

    issue(0, 0);

    float acc[4][4][4];
#pragma unroll
    for (int a = 0; a < 4; a++)
#pragma unroll
        for (int b = 0; b < 4; b++)
#pragma unroll
            for (int c = 0; c < 4; c++) acc[a][b][c] = 0.f;

    CP_WAIT0();
    __syncthreads();

    for (int kk = 0; kk < 8; kk++) {
        int buf = kk & 1;
        if (kk < 7) issue(kk + 1, buf ^ 1);
        const __half* A = sm16 + buf * TILE16;
        const __half* B = sm16 + (2 + buf) * TILE16;
#pragma unroll
        for (int ks = 0; ks < 2; ks++) {
            int kb = ks * 16;
            uint32_t bf[4][2];
#pragma unroll
            for (int nf = 0; nf < 4; nf++) {
                int n = warpN * 32 + nf * 8 + g;
                bf[nf][0] = *(const uint32_t*)&B[n * STRD16 + kb + 2 * t];
                bf[nf][1] = *(const uint32_t*)&B[n * STRD16 + kb + 2 * t + 8];
            }
#pragma unroll
            for (int mf = 0; mf < 4; mf++) {
                int m = warpM * 64 + mf * 16;
                uint32_t a0 = *(const uint32_t*)&A[(m + g) * STRD16 + kb + 2 * t];
                uint32_t a1 = *(const uint32_t*)&A[(m + g + 8) * STRD16 + kb + 2 * t];
                uint32_t a2 = *(const uint32_t*)&A[(m + g) * STRD16 + kb + 2 * t + 8];
                uint32_t a3 = *(const uint32_t*)&A[(m + g + 8) * STRD16 + kb + 2 * t + 8];
#pragma unroll
                for (int nf = 0; nf < 4; nf++)
                    mma16(acc[mf][nf], a0, a1, a2, a3, bf[nf][0], bf[nf][1]);
            }
        }
        CP_WAIT0();
        __syncthreads();
    }

#pragma unroll
    for (int nf = 0; nf < 4; nf++) {
        int col = warpN * 32 + nf * 8 + 2 * t;
        float2 bv = *(const float2*)(bias + col);
        float s0 = 0.f, s1 = 0.f, q0 = 0.f, q1 = 0.f;
#pragma unroll
        for (int mf = 0; mf < 4; mf++) {
#pragma unroll
            for (int hh = 0; hh < 2; hh++) {
                int row = m0 + warpM * 64 + mf * 16 + g + hh * 8;
                float v0 = fmaxf(acc[mf][nf][hh * 2 + 0] + bv.x, 0.f);
                float v1 = fmaxf(acc[mf][nf][hh * 2 + 1] + bv.y, 0.f);
                if (row < NN) {
                    __half2 p = __float22half2_rn(make_float2(v0, v1));
                    *(__half2*)(g_rst16 + (size_t)row * DD + col) = p;
                    s0 += v0; q0 += v0 * v0;
                    s1 += v1; q1 += v1 * v1;
                }
            }
        }
        atomicAdd(&cs[col], s0);     atomicAdd(&cs[col + 1], s1);
        atomicAdd(&cq[col], q0);     atomicAdd(&cq[col + 1], q1);
    }
    __syncthreads();
    if (tid < 128) {
        atomicAdd(&g_colsum[tid], cs[tid]);
        atomicAdd(&g_colsumsq[tid], cq[tid]);
    }
}

// ---------------------------------------------------------------- normalize + residual (BN fold inline)
__global__ __launch_bounds__(256) void k_final(const float* __restrict__ h,
                                               const float* __restrict__ gamma,
                                               const float* __restrict__ beta,
                                               float* __restrict__ out) {
    __shared__ float s_scale[DD];
    __shared__ float s_shift[DD];
    if (threadIdx.x < DD) {
        int j = threadIdx.x;
        float mean = g_colsum[j] / (float)NN;
        float var = g_colsumsq[j] / (float)NN - mean * mean;
        float rs = rsqrtf(var + BN_EPS);
        float sc = rs * gamma[j];
        s_scale[j] = sc;
        s_shift[j] = beta[j] - mean * sc;
    }
    __syncthreads();

    int i4 = blockIdx.x * blockDim.x + threadIdx.x;
    const int TOT = NN * DD / 4;
    if (i4 >= TOT) return;
    int c4 = i4 & 31;
    uint2 u = ((const uint2*)g_rst16)[i4];
    float2 r0 = __half22float2(*(__half2*)&u.x);
    float2 r1 = __half22float2(*(__half2*)&u.y);
    float4 hv = ((const float4*)h)[i4];
    float4 sc = *((const float4*)s_scale + c4);
    float4 sh = *((const float4*)s_shift + c4);
    float4 o;
    o.x = hv.x + r0.x * sc.x + sh.x;
    o.y = hv.y + r0.y * sc.y + sh.y;
    o.z = hv.z + r1.x * sc.z + sh.z;
    o.w = hv.w + r1.y * sc.w + sh.w;
    ((float4*)out)[i4] = o;
}

// ---------------------------------------------------------------- launch
extern "C" void kernel_launch(void* const* d_in, const int* in_sizes, int n_in,
                              void* d_out, int out_size) {
    const float* h     = (const float*)d_in[0];
    const int*   src   = (const int*)d_in[1];
    const int*   dst   = (const int*)d_in[2];
    const float* Ws    = (const float*)d_in[3];
    const float* Wn    = (const float*)d_in[4];
    const float* bias  = (const float*)d_in[5];
    const float* gamma = (const float*)d_in[6];
    const float* beta  = (const float*)d_in[7];
    float* out = (float*)d_out;

    const int GEMM_SMEM = 4 * TILE16 * 2 + 256 * 4;
    static bool attr_set = false;
    if (!attr_set) {
        cudaFuncSetAttribute(k_gemm, cudaFuncAttributeMaxDynamicSharedMemorySize, GEMM_SMEM);
        attr_set = true;
    }

    k_zero<<<(NN + 255) / 256, 256>>>();
    k_build<<<FUSED_BLOCKS, 256>>>(dst, src, h, Ws, Wn);
    k_aggregate<<<(NN * 32 + 255) / 256, 256>>>();
    k_gemm<<<(NN + 127) / 128, 256, GEMM_SMEM>>>(bias);
    k_final<<<(NN * DD / 4 + 255) / 256, 256>>>(h, gamma, beta, out);
}

// round 14
// speedup vs baseline: 1.2769x; 1.0325x over previous
#include <cuda_runtime.h>
#include <cuda_fp16.h>
#include <cstdint>

#define NN 100000
#define EE 3200000
#define DD 128
#define BN_EPS 1e-5f
#define CAP 64                         // slots per node (deg ~ Poisson(32))
#define MAXOVF (1 << 18)               // overflow capacity (pairs)

#define EDGE_BLOCKS (EE / 4 / 256)            // 3125
#define H16_BLOCKS  (NN * DD / 8 / 256 + 1)   // 6251
#define WT_BLOCKS   (128 * 256 / 256)         // 128
#define FUSED_BLOCKS (EDGE_BLOCKS + H16_BLOCKS + WT_BLOCKS)

// ---- scratch (device globals) ----
__device__ int    g_count[NN];
__device__ int    g_slots[(size_t)NN * CAP];   // src indices, slot r = rank r
__device__ int    g_ovf[2 * MAXOVF];           // (dst, src) pairs for rank >= CAP
__device__ int    g_ovf_ctr;
__device__ __half g_h16[(size_t)NN * DD];
__device__ __half g_neigh16[(size_t)NN * DD];
__device__ __half g_rst16[(size_t)NN * DD];
__device__ __half g_Wt16[128 * 256];           // [n][k] fp16 W^T over [W_self; W_neigh]
__device__ float  g_colsum[DD];
__device__ float  g_colsumsq[DD];

// ================= helpers =================
__device__ __forceinline__ uint32_t smem_u32(const void* p) {
    uint32_t a;
    asm("{ .reg .u64 t; cvta.to.shared.u64 t, %1; cvt.u32.u64 %0, t; }" : "=r"(a) : "l"(p));
    return a;
}
__device__ __forceinline__ void cp16(uint32_t saddr, const void* gaddr, bool valid) {
    asm volatile("cp.async.cg.shared.global [%0], [%1], 16, %2;"
                 :: "r"(saddr), "l"(gaddr), "r"(valid ? 16u : 0u) : "memory");
}
#define CP_COMMIT() asm volatile("cp.async.commit_group;" ::: "memory")
#define CP_WAIT0()  asm volatile("cp.async.wait_group 0;" ::: "memory")

__device__ __forceinline__ void mma16(float* d, uint32_t a0, uint32_t a1, uint32_t a2,
                                      uint32_t a3, uint32_t b0, uint32_t b1) {
    asm volatile(
        "mma.sync.aligned.m16n8k16.row.col.f32.f16.f16.f32 "
        "{%0,%1,%2,%3}, {%4,%5,%6,%7}, {%8,%9}, {%0,%1,%2,%3};"
        : "+f"(d[0]), "+f"(d[1]), "+f"(d[2]), "+f"(d[3])
        : "r"(a0), "r"(a1), "r"(a2), "r"(a3), "r"(b0), "r"(b1));
}
__device__ __forceinline__ void ldsm_x4(uint32_t& r0, uint32_t& r1, uint32_t& r2,
                                        uint32_t& r3, uint32_t addr) {
    asm volatile("ldmatrix.sync.aligned.m8n8.x4.shared.b16 {%0,%1,%2,%3}, [%4];"
                 : "=r"(r0), "=r"(r1), "=r"(r2), "=r"(r3) : "r"(addr));
}

// ---------------------------------------------------------------- zero
__global__ void k_zero() {
    int i = blockIdx.x * blockDim.x + threadIdx.x;
    if (i < NN) g_count[i] = 0;
    if (i < DD) { g_colsum[i] = 0.f; g_colsumsq[i] = 0.f; }
    if (i == 0) g_ovf_ctr = 0;
}

// ---------------------------------------------------------------- fused: edge-slot build | h->fp16 | W^T fp16
__device__ __forceinline__ void place_edge(int d, int s) {
    int r = atomicAdd(&g_count[d], 1);
    if (r < CAP) {
        g_slots[(size_t)d * CAP + r] = s;
    } else {
        int idx = atomicAdd(&g_ovf_ctr, 1);
        if (idx < MAXOVF) { g_ovf[2 * idx] = d; g_ovf[2 * idx + 1] = s; }
    }
}
__global__ void k_build(const int* __restrict__ dst,
                        const int* __restrict__ src,
                        const float* __restrict__ h,
                        const float* __restrict__ Ws,
                        const float* __restrict__ Wn) {
    int b = blockIdx.x;
    if (b < EDGE_BLOCKS) {
        int e4 = b * 256 + threadIdx.x;
        if (e4 >= EE / 4) return;
        int4 d = ((const int4*)dst)[e4];
        int4 s = ((const int4*)src)[e4];
        place_edge(d.x, s.x);
        place_edge(d.y, s.y);
        place_edge(d.z, s.z);
        place_edge(d.w, s.w);
    } else if (b < EDGE_BLOCKS + H16_BLOCKS) {
        int i = (b - EDGE_BLOCKS) * 256 + threadIdx.x;
        const int TOT = NN * DD / 8;
        if (i >= TOT) return;
        float4 a = ((const float4*)h)[2 * i];
        float4 bb = ((const float4*)h)[2 * i + 1];
        __half2 r[4];
        r[0] = __float22half2_rn(make_float2(a.x, a.y));
        r[1] = __float22half2_rn(make_float2(a.z, a.w));
        r[2] = __float22half2_rn(make_float2(bb.x, bb.y));
        r[3] = __float22half2_rn(make_float2(bb.z, bb.w));
        ((uint4*)g_h16)[i] = *(uint4*)r;
    } else {
        int i = (b - EDGE_BLOCKS - H16_BLOCKS) * 256 + threadIdx.x;
        if (i >= 128 * 256) return;
        int n = i >> 8, k = i & 255;
        float v = (k < 128) ? Ws[(size_t)k * DD + n] : Wn[(size_t)(k - 128) * DD + n];
        g_Wt16[i] = __float2half_rn(v);
    }
}

// ---------------------------------------------------------------- segment mean (1 warp / node, fp16 gather)
__global__ void k_aggregate() {
    int gwarp = (blockIdx.x * blockDim.x + threadIdx.x) >> 5;
    if (gwarp >= NN) return;
    int lane = threadIdx.x & 31;
    int start = gwarp * CAP;
    int deg = g_count[gwarp];
    int main_n = (deg < CAP) ? deg : CAP;

    float accA[4] = {0, 0, 0, 0};
    float accB[4] = {0, 0, 0, 0};

    int i = 0;
    for (; i + 32 <= main_n; i += 32) {
        int s = g_slots[start + i + lane];
#pragma unroll
        for (int j = 0; j < 32; j += 2) {
            int s0 = __shfl_sync(0xffffffffu, s, j);
            int s1 = __shfl_sync(0xffffffffu, s, j + 1);
            uint2 u0 = *((const uint2*)(g_h16 + (size_t)s0 * DD) + lane);
            uint2 u1 = *((const uint2*)(g_h16 + (size_t)s1 * DD) + lane);
            {
                float2 f0 = __half22float2(*(__half2*)&u0.x);
                float2 f1 = __half22float2(*(__half2*)&u0.y);
                accA[0] += f0.x; accA[1] += f0.y; accA[2] += f1.x; accA[3] += f1.y;
            }
            {
                float2 f0 = __half22float2(*(__half2*)&u1.x);
                float2 f1 = __half22float2(*(__half2*)&u1.y);
                accB[0] += f0.x; accB[1] += f0.y; accB[2] += f1.x; accB[3] += f1.y;
            }
        }
    }
    {
        int rem = main_n - i;
        int s = (lane < rem) ? g_slots[start + i + lane] : 0;
        for (int j = 0; j < rem; j++) {
            int sj = __shfl_sync(0xffffffffu, s, j);
            uint2 u = *((const uint2*)(g_h16 + (size_t)sj * DD) + lane);
            float2 f0 = __half22float2(*(__half2*)&u.x);
            float2 f1 = __half22float2(*(__half2*)&u.y);
            accA[0] += f0.x; accA[1] += f0.y; accA[2] += f1.x; accA[3] += f1.y;
        }
    }
    if (deg > CAP) {
        int n = g_ovf_ctr;
        if (n > MAXOVF) n = MAXOVF;
        for (int o = 0; o < n; o++) {
            if (g_ovf[2 * o] == gwarp) {
                int sj = g_ovf[2 * o + 1];
                uint2 u = *((const uint2*)(g_h16 + (size_t)sj * DD) + lane);
                float2 f0 = __half22float2(*(__half2*)&u.x);
                float2 f1 = __half22float2(*(__half2*)&u.y);
                accA[0] += f0.x; accA[1] += f0.y; accA[2] += f1.x; accA[3] += f1.y;
            }
        }
    }
    float inv = 1.0f / fmaxf((float)deg, 1.0f);
    __half2 p0 = __float22half2_rn(make_float2((accA[0] + accB[0]) * inv,
                                               (accA[1] + accB[1]) * inv));
    __half2 p1 = __float22half2_rn(make_float2((accA[2] + accB[2]) * inv,
                                               (accA[3] + accB[3]) * inv));
    uint2 o;
    o.x = *(uint32_t*)&p0;
    o.y = *(uint32_t*)&p1;
    *((uint2*)(g_neigh16 + (size_t)gwarp * DD) + lane) = o;
}

// ---------------------------------------------------------------- FP16 mma.sync GEMM (ldmatrix fragments)
#define STRD16 40
#define TILE16 (128 * STRD16)
__global__ __launch_bounds__(256, 2) void k_gemm(const float* __restrict__ bias) {
    extern __shared__ __half sm16[];
    float* cs = (float*)(sm16 + 4 * TILE16);
    float* cq = cs + 128;

    int tid = threadIdx.x;
    int wid = tid >> 5, lane = tid & 31;
    int g = lane >> 2, t = lane & 3;
    int warpM = wid >> 2, warpN = wid & 3;
    int m0 = blockIdx.x * 128;

    if (tid < 128) { cs[tid] = 0.f; cq[tid] = 0.f; }

    uint32_t sb = smem_u32(sm16);

    // ldmatrix per-lane address components (in halves)
    int lane7 = lane & 7;
    int aRow = ((lane >> 3) & 1) * 8 + lane7;   // + m tile base
    int aK   = ((lane >> 4) & 1) * 8;           // + kb
    int bRow = ((lane >> 4) & 1) * 8 + lane7;   // + n0
    int bK   = ((lane >> 3) & 1) * 8;           // + kb

    auto issue = [&](int kk, int buf) {
        uint32_t abase = sb + (uint32_t)(buf * TILE16) * 2u;
#pragma unroll
        for (int i = 0; i < 2; i++) {
            int slot = tid + i * 256;
            int row = slot >> 2, seg = slot & 3;
            int gm = m0 + row;
            const __half* gp = (kk < 4)
                ? (g_h16 + (size_t)gm * DD + kk * 32 + seg * 8)
                : (g_neigh16 + (size_t)gm * DD + (kk - 4) * 32 + seg * 8);
            cp16(abase + row * (STRD16 * 2) + seg * 16, gp, gm < NN);
        }
        uint32_t bbase = sb + (uint32_t)((2 + buf) * TILE16) * 2u;
#pragma unroll
        for (int i = 0; i < 2; i++) {
            int slot = tid + i * 256;
            int row = slot >> 2, seg = slot & 3;
            cp16(bbase + row * (STRD16 * 2) + seg * 16,
                 g_Wt16 + (size_t)row * 256 + kk * 32 + seg * 8, true);
        }
        CP_COMMIT();
    };

    issue(0, 0);

    float acc[4][4][4];
#pragma unroll
    for (int a = 0; a < 4; a++)
#pragma unroll
        for (int b = 0; b < 4; b++)
#pragma unroll
            for (int c = 0; c < 4; c++) acc[a][b][c] = 0.f;

    CP_WAIT0();
    __syncthreads();

    for (int kk = 0; kk < 8; kk++) {
        int buf = kk & 1;
        if (kk < 7) issue(kk + 1, buf ^ 1);
        uint32_t ab = sb + (uint32_t)(buf * TILE16) * 2u;
        uint32_t bb = sb + (uint32_t)((2 + buf) * TILE16) * 2u;
#pragma unroll
        for (int ks = 0; ks < 2; ks++) {
            int kb = ks * 16;
            uint32_t bf[4][2];
#pragma unroll
            for (int pair = 0; pair < 2; pair++) {
                int n0 = warpN * 32 + pair * 16;
                uint32_t addr = bb + (uint32_t)((n0 + bRow) * STRD16 + kb + bK) * 2u;
                ldsm_x4(bf[2 * pair][0], bf[2 * pair][1],
                        bf[2 * pair + 1][0], bf[2 * pair + 1][1], addr);
            }
#pragma unroll
            for (int mf = 0; mf < 4; mf++) {
                int m = warpM * 64 + mf * 16;
                uint32_t a0, a1, a2, a3;
                uint32_t addr = ab + (uint32_t)((m + aRow) * STRD16 + kb + aK) * 2u;
                ldsm_x4(a0, a1, a2, a3, addr);
#pragma unroll
                for (int nf = 0; nf < 4; nf++)
                    mma16(acc[mf][nf], a0, a1, a2, a3, bf[nf][0], bf[nf][1]);
            }
        }
        CP_WAIT0();
        __syncthreads();
    }

#pragma unroll
    for (int nf = 0; nf < 4; nf++) {
        int col = warpN * 32 + nf * 8 + 2 * t;
        float2 bv = *(const float2*)(bias + col);
        float s0 = 0.f, s1 = 0.f, q0 = 0.f, q1 = 0.f;
#pragma unroll
        for (int mf = 0; mf < 4; mf++) {
#pragma unroll
            for (int hh = 0; hh < 2; hh++) {
                int row = m0 + warpM * 64 + mf * 16 + g + hh * 8;
                float v0 = fmaxf(acc[mf][nf][hh * 2 + 0] + bv.x, 0.f);
                float v1 = fmaxf(acc[mf][nf][hh * 2 + 1] + bv.y, 0.f);
                if (row < NN) {
                    __half2 p = __float22half2_rn(make_float2(v0, v1));
                    *(__half2*)(g_rst16 + (size_t)row * DD + col) = p;
                    s0 += v0; q0 += v0 * v0;
                    s1 += v1; q1 += v1 * v1;
                }
            }
        }
        atomicAdd(&cs[col], s0);     atomicAdd(&cs[col + 1], s1);
        atomicAdd(&cq[col], q0);     atomicAdd(&cq[col + 1], q1);
    }
    __syncthreads();
    if (tid < 128) {
        atomicAdd(&g_colsum[tid], cs[tid]);
        atomicAdd(&g_colsumsq[tid], cq[tid]);
    }
}

// ---------------------------------------------------------------- normalize + residual (BN fold inline)
__global__ __launch_bounds__(256) void k_final(const float* __restrict__ h,
                                               const float* __restrict__ gamma,
                                               const float* __restrict__ beta,
                                               float* __restrict__ out) {
    __shared__ float s_scale[DD];
    __shared__ float s_shift[DD];
    if (threadIdx.x < DD) {
        int j = threadIdx.x;
        float mean = g_colsum[j] / (float)NN;
        float var = g_colsumsq[j] / (float)NN - mean * mean;
        float rs = rsqrtf(var + BN_EPS);
        float sc = rs * gamma[j];
        s_scale[j] = sc;
        s_shift[j] = beta[j] - mean * sc;
    }
    __syncthreads();

    int i4 = blockIdx.x * blockDim.x + threadIdx.x;
    const int TOT = NN * DD / 4;
    if (i4 >= TOT) return;
    int c4 = i4 & 31;
    uint2 u = ((const uint2*)g_rst16)[i4];
    float2 r0 = __half22float2(*(__half2*)&u.x);
    float2 r1 = __half22float2(*(__half2*)&u.y);
    float4 hv = ((const float4*)h)[i4];
    float4 sc = *((const float4*)s_scale + c4);
    float4 sh = *((const float4*)s_shift + c4);
    float4 o;
    o.x = hv.x + r0.x * sc.x + sh.x;
    o.y = hv.y + r0.y * sc.y + sh.y;
    o.z = hv.z + r1.x * sc.z + sh.z;
    o.w = hv.w + r1.y * sc.w + sh.w;
    ((float4*)out)[i4] = o;
}

// ---------------------------------------------------------------- launch
extern "C" void kernel_launch(void* const* d_in, const int* in_sizes, int n_in,
                              void* d_out, int out_size) {
    const float* h     = (const float*)d_in[0];
    const int*   src   = (const int*)d_in[1];
    const int*   dst   = (const int*)d_in[2];
    const float* Ws    = (const float*)d_in[3];
    const float* Wn    = (const float*)d_in[4];
    const float* bias  = (const float*)d_in[5];
    const float* gamma = (const float*)d_in[6];
    const float* beta  = (const float*)d_in[7];
    float* out = (float*)d_out;

    const int GEMM_SMEM = 4 * TILE16 * 2 + 256 * 4;
    static bool attr_set = false;
    if (!attr_set) {
        cudaFuncSetAttribute(k_gemm, cudaFuncAttributeMaxDynamicSharedMemorySize, GEMM_SMEM);
        attr_set = true;
    }

    k_zero<<<(NN + 255) / 256, 256>>>();
    k_build<<<FUSED_BLOCKS, 256>>>(dst, src, h, Ws, Wn);
    k_aggregate<<<(NN * 32 + 255) / 256, 256>>>();
    k_gemm<<<(NN + 127) / 128, 256, GEMM_SMEM>>>(bias);
    k_final<<<(NN * DD / 4 + 255) / 256, 256>>>(h, gamma, beta, out);
}